// round 13
// baseline (speedup 1.0000x reference)
#include <cuda_runtime.h>
#include <cuda_fp16.h>
#include <mma.h>
#include <math.h>
#include <stdint.h>

using namespace nvcuda;

#define NV      6144
#define NFEAT   128
#define NHID    64
#define NHEAD   4
#define NCLASS  16
#define CAP     256
#define ALPHA   0.2f
#define NEGV    (-1e10f)
#define LDA     136   // 128 + 8 halfs pad
#define LDB     72    // 64 + 8 halfs pad
#define GEMM_BLOCKS 384

// ---------------- device scratch ----------------
__device__ __half g_Hh[(size_t)NV * NHEAD * NHID];
__device__ float  g_s[NHEAD * NV];
__device__ float  g_t[NHEAD * NV];
__device__ int    g_nbr[(size_t)NV * CAP];
__device__ int    g_cnt[NV];
__device__ float  g_H2[(size_t)NV * NCLASS];
__device__ float  g_s2[NV];
__device__ float  g_t2[NV];

__device__ __forceinline__ float lrelu(float x) { return x > 0.f ? x : ALPHA * x; }
__device__ __forceinline__ float eluf(float x)  { return x > 0.f ? x : (__expf(x) - 1.f); }

// ---------------- K1 fat: wmma GEMM blocks + adj-scan blocks (overlapped, no spin) ----------------
__global__ void __launch_bounds__(256) k_fat(const float* __restrict__ adj,
                                             const float* __restrict__ feat,
                                             const float* __restrict__ W0,
                                             const float* __restrict__ a1g,
                                             const float* __restrict__ a2g) {
    __shared__ __align__(16) __half AsH[64 * LDA];
    __shared__ __align__(16) __half BsH[128 * LDB];
    int tid = threadIdx.x;

    if (blockIdx.x < GEMM_BLOCKS) {
        // ============ wmma GEMM branch ============
        float* Cs = reinterpret_cast<float*>(AsH);
        int head = blockIdx.x & 3;
        int row0 = (blockIdx.x >> 2) * 64;
        const float4* feat4 = reinterpret_cast<const float4*>(feat);
        const float4* w04 = reinterpret_cast<const float4*>(W0 + (size_t)head * 512 * 64);
#pragma unroll
        for (int it = 0; it < 8; it++) {
            int idx = it * 256 + tid;
            int r = idx >> 5, c4 = idx & 31;
            float4 v = feat4[(size_t)(row0 + r) * 32 + c4];
            __half2 h0 = __floats2half2_rn(v.x, v.y);
            __half2 h1 = __floats2half2_rn(v.z, v.w);
            uint2 st;
            st.x = *reinterpret_cast<unsigned*>(&h0);
            st.y = *reinterpret_cast<unsigned*>(&h1);
            *reinterpret_cast<uint2*>(&AsH[r * LDA + c4 * 4]) = st;
        }
#pragma unroll
        for (int it = 0; it < 8; it++) {
            int idx = it * 256 + tid;
            int k = idx >> 4, c4 = idx & 15;
            float4 b = make_float4(0.f, 0.f, 0.f, 0.f);
#pragma unroll
            for (int t = 0; t < 4; t++) {
                float4 v = __ldg(&w04[(size_t)(t * 128 + k) * 16 + c4]);
                b.x += v.x; b.y += v.y; b.z += v.z; b.w += v.w;
            }
            __half2 h0 = __floats2half2_rn(b.x, b.y);
            __half2 h1 = __floats2half2_rn(b.z, b.w);
            uint2 st;
            st.x = *reinterpret_cast<unsigned*>(&h0);
            st.y = *reinterpret_cast<unsigned*>(&h1);
            *reinterpret_cast<uint2*>(&BsH[k * LDB + c4 * 4]) = st;
        }
        __syncthreads();

        int warp = tid >> 5;
        int wr = (warp >> 1) * 16;
        int wc = (warp & 1) * 32;
        wmma::fragment<wmma::accumulator, 16, 16, 16, float> c0, c1;
        wmma::fill_fragment(c0, 0.f);
        wmma::fill_fragment(c1, 0.f);
#pragma unroll
        for (int k0 = 0; k0 < 128; k0 += 16) {
            wmma::fragment<wmma::matrix_a, 16, 16, 16, __half, wmma::row_major> a;
            wmma::fragment<wmma::matrix_b, 16, 16, 16, __half, wmma::row_major> b0, b1;
            wmma::load_matrix_sync(a, &AsH[wr * LDA + k0], LDA);
            wmma::load_matrix_sync(b0, &BsH[k0 * LDB + wc], LDB);
            wmma::load_matrix_sync(b1, &BsH[k0 * LDB + wc + 16], LDB);
            wmma::mma_sync(c0, a, b0, c0);
            wmma::mma_sync(c1, a, b1, c1);
        }
        __syncthreads();
        wmma::store_matrix_sync(&Cs[wr * 64 + wc], c0, 64, wmma::mem_row_major);
        wmma::store_matrix_sync(&Cs[wr * 64 + wc + 16], c1, 64, wmma::mem_row_major);
        __syncthreads();

        int r = tid >> 2, q = tid & 3;
        const float* crow = &Cs[r * 64 + q * 16];
        float sa = 0.f, sb = 0.f;
        __half hbuf[16];
#pragma unroll
        for (int c = 0; c < 16; c++) {
            float v = crow[c];
            hbuf[c] = __float2half_rn(v);
            sa += v * __ldg(&a1g[head * 64 + q * 16 + c]);
            sb += v * __ldg(&a2g[head * 64 + q * 16 + c]);
        }
        uint4* dst = reinterpret_cast<uint4*>(&g_Hh[(size_t)(row0 + r) * 256 + head * 64 + q * 16]);
        const uint4* src = reinterpret_cast<const uint4*>(hbuf);
        dst[0] = src[0];
        dst[1] = src[1];
        sa += __shfl_down_sync(0xffffffffu, sa, 2, 4);
        sa += __shfl_down_sync(0xffffffffu, sa, 1, 4);
        sb += __shfl_down_sync(0xffffffffu, sb, 2, 4);
        sb += __shfl_down_sync(0xffffffffu, sb, 1, 4);
        if (q == 0) {
            g_s[head * NV + row0 + r] = sa;
            g_t[head * NV + row0 + r] = sb;
        }
    } else {
        // ============ adj-scan branch ============
        int* wsum = reinterpret_cast<int*>(AsH);   // reuse smem
        int row = blockIdx.x - GEMM_BLOCKS;
        int lane = tid & 31, warp = tid >> 5;
        const uint4* a4 = reinterpret_cast<const uint4*>(adj) + (size_t)row * (NV / 4);
        uint4 v[6];
#pragma unroll
        for (int it = 0; it < 6; it++) v[it] = __ldg(&a4[it * 256 + tid]);
        unsigned mask = 0;
#pragma unroll
        for (int it = 0; it < 6; it++) {
            if (v[it].x) mask |= 1u << (it * 4 + 0);
            if (v[it].y) mask |= 1u << (it * 4 + 1);
            if (v[it].z) mask |= 1u << (it * 4 + 2);
            if (v[it].w) mask |= 1u << (it * 4 + 3);
        }
        int c = __popc(mask);
        int incl = c;
#pragma unroll
        for (int o = 1; o < 32; o <<= 1) {
            int n = __shfl_up_sync(0xffffffffu, incl, o);
            if (lane >= o) incl += n;
        }
        if (lane == 31) wsum[warp] = incl;
        __syncthreads();
        int base = 0;
#pragma unroll
        for (int w = 0; w < 8; w++) if (w < warp) base += wsum[w];
        int pos = base + incl - c;
        int* out = g_nbr + (size_t)row * CAP;
        while (mask) {
            int b = __ffs(mask) - 1;
            mask &= mask - 1;
            if (pos < CAP) out[pos] = (b >> 2) * 1024 + tid * 4 + (b & 3);
            pos++;
        }
        if (tid == 255) g_cnt[row] = base + incl;
    }
}

// ---------------- K2: hidden attention (reads g_nbr) + fused out-proj ----------------
__global__ void __launch_bounds__(256) k_attn_hidden(const float* __restrict__ adj,
                                                     const float* __restrict__ Wout,
                                                     const float* __restrict__ a1o,
                                                     const float* __restrict__ a2o) {
    int row = blockIdx.x;
    int tid = threadIdx.x;
    int warp = tid >> 5, lane = tid & 31;
    __shared__ int    s_idx[CAP];
    __shared__ float  s_w[NHEAD][CAP];
    __shared__ float  s_stat[NHEAD];
    __shared__ float4 part[4][64];
    __shared__ float  s_x2[256];
    __shared__ float  part2[16][16];
    __shared__ float  red[256];

    int cnt = g_cnt[row];
    bool sparse = (cnt > 0 && cnt <= CAP);
    if (sparse)
        for (int k = tid; k < cnt; k += 256) s_idx[k] = g_nbr[(size_t)row * CAP + k];
    __syncthreads();

    if (sparse) {
        if (warp < 4) {
            float s_i = g_s[warp * NV + row];
            const float* tv = g_t + warp * NV;
            float mx = -INFINITY;
            for (int k = lane; k < cnt; k += 32) {
                float lv = lrelu(s_i + __ldg(&tv[s_idx[k]]));
                s_w[warp][k] = lv;
                mx = fmaxf(mx, lv);
            }
#pragma unroll
            for (int o = 16; o > 0; o >>= 1) mx = fmaxf(mx, __shfl_xor_sync(0xffffffffu, mx, o));
            float sum = 0.f;
            for (int k = lane; k < cnt; k += 32) {
                float e = __expf(s_w[warp][k] - mx);
                s_w[warp][k] = e;
                sum += e;
            }
#pragma unroll
            for (int o = 16; o > 0; o >>= 1) sum += __shfl_xor_sync(0xffffffffu, sum, o);
            if (lane == 0) s_stat[warp] = sum;
        }
        __syncthreads();
        int q = tid >> 6, c4 = tid & 63;
        int hh = c4 >> 4;
        float4 acc = make_float4(0.f, 0.f, 0.f, 0.f);
        const uint2* hrow = reinterpret_cast<const uint2*>(g_Hh);
        int k = q;
        for (; k + 4 < cnt; k += 8) {
            float w0 = s_w[hh][k], w1 = s_w[hh][k + 4];
            uint2 r0 = __ldg(&hrow[(size_t)s_idx[k] * 64 + c4]);
            uint2 r1 = __ldg(&hrow[(size_t)s_idx[k + 4] * 64 + c4]);
            float2 f00 = __half22float2(*reinterpret_cast<__half2*>(&r0.x));
            float2 f01 = __half22float2(*reinterpret_cast<__half2*>(&r0.y));
            float2 f10 = __half22float2(*reinterpret_cast<__half2*>(&r1.x));
            float2 f11 = __half22float2(*reinterpret_cast<__half2*>(&r1.y));
            acc.x += w0 * f00.x + w1 * f10.x;
            acc.y += w0 * f00.y + w1 * f10.y;
            acc.z += w0 * f01.x + w1 * f11.x;
            acc.w += w0 * f01.y + w1 * f11.y;
        }
        for (; k < cnt; k += 4) {
            float w = s_w[hh][k];
            uint2 raw = __ldg(&hrow[(size_t)s_idx[k] * 64 + c4]);
            float2 f0 = __half22float2(*reinterpret_cast<__half2*>(&raw.x));
            float2 f1 = __half22float2(*reinterpret_cast<__half2*>(&raw.y));
            acc.x += w * f0.x; acc.y += w * f0.y; acc.z += w * f1.x; acc.w += w * f1.y;
        }
        part[q][c4] = acc;
        __syncthreads();
        if (q == 0) {
            float4 p0 = part[0][c4], p1 = part[1][c4], p2 = part[2][c4], p3 = part[3][c4];
            float S = s_stat[hh];
            s_x2[c4 * 4 + 0] = eluf((p0.x + p1.x + p2.x + p3.x) / S);
            s_x2[c4 * 4 + 1] = eluf((p0.y + p1.y + p2.y + p3.y) / S);
            s_x2[c4 * 4 + 2] = eluf((p0.z + p1.z + p2.z + p3.z) / S);
            s_x2[c4 * 4 + 3] = eluf((p0.w + p1.w + p2.w + p3.w) / S);
        }
    } else {
        int g = tid >> 6, l = tid & 63;
        const float* arow = adj + (size_t)row * NV;
        float s_i = g_s[g * NV + row];
        const float* tvec = g_t + g * NV;
        float mx = -INFINITY;
        for (int j = l; j < NV; j += 64) {
            float lv = lrelu(s_i + tvec[j]);
            if (arow[j] == 0.f) lv += NEGV;
            mx = fmaxf(mx, lv);
        }
        red[tid] = mx; __syncthreads();
        if (l < 32) {
            float m = fmaxf(red[tid], red[tid + 32]);
#pragma unroll
            for (int o = 16; o > 0; o >>= 1) m = fmaxf(m, __shfl_xor_sync(0xffffffffu, m, o));
            if (l == 0) s_stat[g] = m;
        }
        __syncthreads();
        mx = s_stat[g];
        float sum = 0.f;
        for (int j = l; j < NV; j += 64) {
            float lv = lrelu(s_i + tvec[j]);
            if (arow[j] == 0.f) lv += NEGV;
            sum += __expf(lv - mx);
        }
        __syncthreads();
        red[tid] = sum; __syncthreads();
        if (l < 32) {
            float s = red[tid] + red[tid + 32];
#pragma unroll
            for (int o = 16; o > 0; o >>= 1) s += __shfl_xor_sync(0xffffffffu, s, o);
            if (l == 0) s_stat[g] = s;
        }
        __syncthreads();
        float S = s_stat[g];
        float acc = 0.f;
        const __half* hb = g_Hh + g * 64 + l;
        for (int j = 0; j < NV; j++) {
            float lv = lrelu(s_i + tvec[j]);
            if (arow[j] == 0.f) lv += NEGV;
            acc += __expf(lv - mx) * __half2float(hb[(size_t)j * 256]);
        }
        s_x2[g * 64 + l] = eluf(acc / S);
    }
    __syncthreads();

    // ---- fused out-projection (Wout via L1) ----
    {
        int c = tid & 15, kq = tid >> 4;
        float acc = 0.f;
#pragma unroll
        for (int k = 0; k < 16; k++)
            acc += s_x2[kq * 16 + k] * __ldg(&Wout[(kq * 16 + k) * 16 + c]);
        part2[kq][c] = acc;
    }
    __syncthreads();
    if (tid < 16) {
        float h = 0.f;
#pragma unroll
        for (int w = 0; w < 16; w++) h += part2[w][tid];
        g_H2[(size_t)row * 16 + tid] = h;
        float sa = h * __ldg(&a1o[tid]), sb = h * __ldg(&a2o[tid]);
#pragma unroll
        for (int o = 8; o > 0; o >>= 1) {
            sa += __shfl_xor_sync(0xffffu, sa, o, 16);
            sb += __shfl_xor_sync(0xffffu, sb, o, 16);
        }
        if (tid == 0) { g_s2[row] = sa; g_t2[row] = sb; }
    }
}

// ---------------- K3: output attention, warp-per-row ----------------
__global__ void __launch_bounds__(128) k_attn_out(const float* __restrict__ adj, float* __restrict__ out) {
    __shared__ float s_w[4][CAP];
    __shared__ int   s_ix[4][CAP];
    int w = threadIdx.x >> 5, lane = threadIdx.x & 31;
    int row = blockIdx.x * 4 + w;
    int cnt = g_cnt[row];
    float s_i = g_s2[row];
    bool sparse = (cnt > 0 && cnt <= CAP);

    if (sparse) {
        const int* nb = g_nbr + (size_t)row * CAP;
        float mx = -INFINITY;
        for (int k = lane; k < cnt; k += 32) {
            int ix = __ldg(&nb[k]);
            s_ix[w][k] = ix;
            float lv = lrelu(s_i + __ldg(&g_t2[ix]));
            s_w[w][k] = lv;
            mx = fmaxf(mx, lv);
        }
#pragma unroll
        for (int o = 16; o > 0; o >>= 1) mx = fmaxf(mx, __shfl_xor_sync(0xffffffffu, mx, o));
        float sum = 0.f;
        for (int k = lane; k < cnt; k += 32) {
            float e = __expf(s_w[w][k] - mx);
            s_w[w][k] = e;
            sum += e;
        }
#pragma unroll
        for (int o = 16; o > 0; o >>= 1) sum += __shfl_xor_sync(0xffffffffu, sum, o);
        __syncwarp();
        int q = lane >> 4, c = lane & 15;
        float acc = 0.f;
        int k = q;
        for (; k + 6 < cnt; k += 8) {
            float w0 = s_w[w][k],     w1 = s_w[w][k + 2];
            float w2 = s_w[w][k + 4], w3 = s_w[w][k + 6];
            int i0 = s_ix[w][k],     i1 = s_ix[w][k + 2];
            int i2 = s_ix[w][k + 4], i3 = s_ix[w][k + 6];
            float v0 = __ldg(&g_H2[(size_t)i0 * 16 + c]);
            float v1 = __ldg(&g_H2[(size_t)i1 * 16 + c]);
            float v2 = __ldg(&g_H2[(size_t)i2 * 16 + c]);
            float v3 = __ldg(&g_H2[(size_t)i3 * 16 + c]);
            acc += w0 * v0 + w1 * v1 + w2 * v2 + w3 * v3;
        }
        for (; k < cnt; k += 2)
            acc += s_w[w][k] * __ldg(&g_H2[(size_t)s_ix[w][k] * 16 + c]);
        acc += __shfl_down_sync(0xffffffffu, acc, 16);
        float v = eluf(acc / sum);
        float m16 = v;
#pragma unroll
        for (int o = 8; o > 0; o >>= 1) m16 = fmaxf(m16, __shfl_xor_sync(0xffffffffu, m16, o, 16));
        float e = __expf(v - m16);
        float se = e;
#pragma unroll
        for (int o = 8; o > 0; o >>= 1) se += __shfl_xor_sync(0xffffffffu, se, o, 16);
        if (lane < 16) out[(size_t)row * 16 + lane] = e / se;
    } else {
        const float* arow = adj + (size_t)row * NV;
        float mx = -INFINITY;
        for (int j = lane; j < NV; j += 32) {
            float lv = lrelu(s_i + g_t2[j]);
            if (arow[j] == 0.f) lv += NEGV;
            mx = fmaxf(mx, lv);
        }
#pragma unroll
        for (int o = 16; o > 0; o >>= 1) mx = fmaxf(mx, __shfl_xor_sync(0xffffffffu, mx, o));
        float sum = 0.f;
        for (int j = lane; j < NV; j += 32) {
            float lv = lrelu(s_i + g_t2[j]);
            if (arow[j] == 0.f) lv += NEGV;
            sum += __expf(lv - mx);
        }
#pragma unroll
        for (int o = 16; o > 0; o >>= 1) sum += __shfl_xor_sync(0xffffffffu, sum, o);
        int q = lane >> 4, c = lane & 15;
        float acc = 0.f;
        for (int j = q; j < NV; j += 2) {
            float lv = lrelu(s_i + g_t2[j]);
            if (arow[j] == 0.f) lv += NEGV;
            acc += __expf(lv - mx) * __ldg(&g_H2[(size_t)j * 16 + c]);
        }
        acc += __shfl_down_sync(0xffffffffu, acc, 16);
        float v = eluf(acc / sum);
        float m16 = v;
#pragma unroll
        for (int o = 8; o > 0; o >>= 1) m16 = fmaxf(m16, __shfl_xor_sync(0xffffffffu, m16, o, 16));
        float e = __expf(v - m16);
        float se = e;
#pragma unroll
        for (int o = 8; o > 0; o >>= 1) se += __shfl_xor_sync(0xffffffffu, se, o, 16);
        if (lane < 16) out[(size_t)row * 16 + lane] = e / se;
    }
}

// ---------------- launch ----------------
extern "C" void kernel_launch(void* const* d_in, const int* in_sizes, int n_in,
                              void* d_out, int out_size) {
    const float* adj  = (const float*)d_in[0];
    const float* feat = (const float*)d_in[1];
    const float* W0   = (const float*)d_in[2];
    const float* a1_0 = (const float*)d_in[3];
    const float* a2_0 = (const float*)d_in[4];
    const float* Wout = (const float*)d_in[5];
    const float* a1o  = (const float*)d_in[6];
    const float* a2o  = (const float*)d_in[7];
    float* out = (float*)d_out;

    k_fat<<<GEMM_BLOCKS + NV, 256>>>(adj, feat, W0, a1_0, a2_0);  // GEMM hidden under adj scan
    k_attn_hidden<<<NV, 256>>>(adj, Wout, a1o, a2o);
    k_attn_out<<<NV / 4, 128>>>(adj, out);
}

// round 14
// speedup vs baseline: 1.2150x; 1.2150x over previous
#include <cuda_runtime.h>
#include <cuda_fp16.h>
#include <mma.h>
#include <math.h>
#include <stdint.h>

using namespace nvcuda;

#define NV      6144
#define NFEAT   128
#define NHID    64
#define NHEAD   4
#define NCLASS  16
#define CAP     256
#define ALPHA   0.2f
#define NEGV    (-1e10f)
#define LDA     136
#define LDB     72

// ---------------- device scratch ----------------
__device__ __half g_Hh[(size_t)NV * NHEAD * NHID];
__device__ float  g_s[NHEAD * NV];
__device__ float  g_t[NHEAD * NV];
__device__ int    g_nbr[(size_t)NV * CAP];
__device__ int    g_cnt[NV];
__device__ float  g_H2[(size_t)NV * NCLASS];
__device__ float  g_s2[NV];
__device__ float  g_t2[NV];

__device__ __forceinline__ float lrelu(float x) { return x > 0.f ? x : ALPHA * x; }
__device__ __forceinline__ float eluf(float x)  { return x > 0.f ? x : (__expf(x) - 1.f); }

// ---------------- K1: tensor-core GEMM (Weff folded in B-load) + fused s/t ----------------
__global__ void __launch_bounds__(256) k_gemm(const float* __restrict__ feat,
                                              const float* __restrict__ W0,
                                              const float* __restrict__ a1g,
                                              const float* __restrict__ a2g) {
    __shared__ __align__(16) __half AsH[64 * LDA];
    __shared__ __align__(16) __half BsH[128 * LDB];
    float* Cs = reinterpret_cast<float*>(AsH);
    int tid = threadIdx.x;
    int head = blockIdx.x & 3;
    int row0 = (blockIdx.x >> 2) * 64;
    const float4* feat4 = reinterpret_cast<const float4*>(feat);
    const float4* w04 = reinterpret_cast<const float4*>(W0 + (size_t)head * 512 * 64);
#pragma unroll
    for (int it = 0; it < 8; it++) {
        int idx = it * 256 + tid;
        int r = idx >> 5, c4 = idx & 31;
        float4 v = feat4[(size_t)(row0 + r) * 32 + c4];
        __half2 h0 = __floats2half2_rn(v.x, v.y);
        __half2 h1 = __floats2half2_rn(v.z, v.w);
        uint2 st;
        st.x = *reinterpret_cast<unsigned*>(&h0);
        st.y = *reinterpret_cast<unsigned*>(&h1);
        *reinterpret_cast<uint2*>(&AsH[r * LDA + c4 * 4]) = st;
    }
#pragma unroll
    for (int it = 0; it < 8; it++) {
        int idx = it * 256 + tid;
        int k = idx >> 4, c4 = idx & 15;
        float4 b = make_float4(0.f, 0.f, 0.f, 0.f);
#pragma unroll
        for (int t = 0; t < 4; t++) {
            float4 v = __ldg(&w04[(size_t)(t * 128 + k) * 16 + c4]);
            b.x += v.x; b.y += v.y; b.z += v.z; b.w += v.w;
        }
        __half2 h0 = __floats2half2_rn(b.x, b.y);
        __half2 h1 = __floats2half2_rn(b.z, b.w);
        uint2 st;
        st.x = *reinterpret_cast<unsigned*>(&h0);
        st.y = *reinterpret_cast<unsigned*>(&h1);
        *reinterpret_cast<uint2*>(&BsH[k * LDB + c4 * 4]) = st;
    }
    __syncthreads();

    int warp = tid >> 5;
    int wr = (warp >> 1) * 16;
    int wc = (warp & 1) * 32;
    wmma::fragment<wmma::accumulator, 16, 16, 16, float> c0, c1;
    wmma::fill_fragment(c0, 0.f);
    wmma::fill_fragment(c1, 0.f);
#pragma unroll
    for (int k0 = 0; k0 < 128; k0 += 16) {
        wmma::fragment<wmma::matrix_a, 16, 16, 16, __half, wmma::row_major> a;
        wmma::fragment<wmma::matrix_b, 16, 16, 16, __half, wmma::row_major> b0, b1;
        wmma::load_matrix_sync(a, &AsH[wr * LDA + k0], LDA);
        wmma::load_matrix_sync(b0, &BsH[k0 * LDB + wc], LDB);
        wmma::load_matrix_sync(b1, &BsH[k0 * LDB + wc + 16], LDB);
        wmma::mma_sync(c0, a, b0, c0);
        wmma::mma_sync(c1, a, b1, c1);
    }
    __syncthreads();
    wmma::store_matrix_sync(&Cs[wr * 64 + wc], c0, 64, wmma::mem_row_major);
    wmma::store_matrix_sync(&Cs[wr * 64 + wc + 16], c1, 64, wmma::mem_row_major);
    __syncthreads();

    int r = tid >> 2, q = tid & 3;
    const float* crow = &Cs[r * 64 + q * 16];
    float sa = 0.f, sb = 0.f;
    __half hbuf[16];
#pragma unroll
    for (int c = 0; c < 16; c++) {
        float v = crow[c];
        hbuf[c] = __float2half_rn(v);
        sa += v * __ldg(&a1g[head * 64 + q * 16 + c]);
        sb += v * __ldg(&a2g[head * 64 + q * 16 + c]);
    }
    uint4* dst = reinterpret_cast<uint4*>(&g_Hh[(size_t)(row0 + r) * 256 + head * 64 + q * 16]);
    const uint4* src = reinterpret_cast<const uint4*>(hbuf);
    dst[0] = src[0];
    dst[1] = src[1];
    sa += __shfl_down_sync(0xffffffffu, sa, 2, 4);
    sa += __shfl_down_sync(0xffffffffu, sa, 1, 4);
    sb += __shfl_down_sync(0xffffffffu, sb, 2, 4);
    sb += __shfl_down_sync(0xffffffffu, sb, 1, 4);
    if (q == 0) {
        g_s[head * NV + row0 + r] = sa;
        g_t[head * NV + row0 + r] = sb;
    }
}

// ---------------- K2: FUSED adj-scan + hidden attention + out-proj ----------------
__global__ void __launch_bounds__(256) k_attn_hidden(const float* __restrict__ adj,
                                                     const float* __restrict__ Wout,
                                                     const float* __restrict__ a1o,
                                                     const float* __restrict__ a2o) {
    int row = blockIdx.x;
    int tid = threadIdx.x;
    int warp = tid >> 5, lane = tid & 31;
    __shared__ int    s_idx[CAP];
    __shared__ float  s_w[NHEAD][CAP];
    __shared__ float  s_stat[NHEAD];
    __shared__ float  partF[8][256];
    __shared__ float  s_x2[256];
    __shared__ float  part2[16][16];
    __shared__ float  red[256];
    __shared__ int    wsum[8];
    __shared__ int    s_cnt;

    // ---- phase 0: scan adj row, compact into smem ----
    {
        const uint4* a4 = reinterpret_cast<const uint4*>(adj) + (size_t)row * (NV / 4);
        uint4 v[6];
#pragma unroll
        for (int it = 0; it < 6; it++) v[it] = __ldg(&a4[it * 256 + tid]);
        unsigned mask = 0;
#pragma unroll
        for (int it = 0; it < 6; it++) {
            if (v[it].x) mask |= 1u << (it * 4 + 0);
            if (v[it].y) mask |= 1u << (it * 4 + 1);
            if (v[it].z) mask |= 1u << (it * 4 + 2);
            if (v[it].w) mask |= 1u << (it * 4 + 3);
        }
        int c = __popc(mask);
        int incl = c;
#pragma unroll
        for (int o = 1; o < 32; o <<= 1) {
            int n = __shfl_up_sync(0xffffffffu, incl, o);
            if (lane >= o) incl += n;
        }
        if (lane == 31) wsum[warp] = incl;
        __syncthreads();
        int base = 0;
#pragma unroll
        for (int w = 0; w < 8; w++) if (w < warp) base += wsum[w];
        int pos = base + incl - c;
        while (mask) {
            int b = __ffs(mask) - 1;
            mask &= mask - 1;
            if (pos < CAP) s_idx[pos] = (b >> 2) * 1024 + tid * 4 + (b & 3);
            pos++;
        }
        if (tid == 255) {
            int total = base + incl;
            s_cnt = total;
            g_cnt[row] = total;
        }
    }
    __syncthreads();
    int cnt = s_cnt;
    bool sparse = (cnt > 0 && cnt <= CAP);
    if (sparse)
        for (int k = tid; k < cnt; k += 256) g_nbr[(size_t)row * CAP + k] = s_idx[k];

    if (sparse) {
        // warp-per-head softmax weights
        if (warp < 4) {
            float s_i = g_s[warp * NV + row];
            const float* tv = g_t + warp * NV;
            float mx = -INFINITY;
            for (int k = lane; k < cnt; k += 32) {
                float lv = lrelu(s_i + __ldg(&tv[s_idx[k]]));
                s_w[warp][k] = lv;
                mx = fmaxf(mx, lv);
            }
#pragma unroll
            for (int o = 16; o > 0; o >>= 1) mx = fmaxf(mx, __shfl_xor_sync(0xffffffffu, mx, o));
            float sum = 0.f;
            for (int k = lane; k < cnt; k += 32) {
                float e = __expf(s_w[warp][k] - mx);
                s_w[warp][k] = e;
                sum += e;
            }
#pragma unroll
            for (int o = 16; o > 0; o >>= 1) sum += __shfl_xor_sync(0xffffffffu, sum, o);
            if (lane == 0) s_stat[warp] = sum;
        }
        __syncthreads();
        // gather: 8 neighbor phases x 32 16B-chunks (8 cols each), uint4 loads
        int q = tid >> 5;          // phase 0..7 (= warp)
        int c8 = lane;             // chunk 0..31 -> cols c8*8..c8*8+7
        int hh = c8 >> 3;          // head
        float a0 = 0.f, a1 = 0.f, a2 = 0.f, a3 = 0.f, a4 = 0.f, a5 = 0.f, a6 = 0.f, a7 = 0.f;
        const uint4* hrow4 = reinterpret_cast<const uint4*>(g_Hh);
        int k = q;
        for (; k + 8 < cnt; k += 16) {
            float w0 = s_w[hh][k], w1 = s_w[hh][k + 8];
            uint4 r0 = __ldg(&hrow4[(size_t)s_idx[k] * 32 + c8]);
            uint4 r1 = __ldg(&hrow4[(size_t)s_idx[k + 8] * 32 + c8]);
            float2 f0 = __half22float2(*reinterpret_cast<__half2*>(&r0.x));
            float2 f1 = __half22float2(*reinterpret_cast<__half2*>(&r0.y));
            float2 f2 = __half22float2(*reinterpret_cast<__half2*>(&r0.z));
            float2 f3 = __half22float2(*reinterpret_cast<__half2*>(&r0.w));
            a0 += w0 * f0.x; a1 += w0 * f0.y; a2 += w0 * f1.x; a3 += w0 * f1.y;
            a4 += w0 * f2.x; a5 += w0 * f2.y; a6 += w0 * f3.x; a7 += w0 * f3.y;
            f0 = __half22float2(*reinterpret_cast<__half2*>(&r1.x));
            f1 = __half22float2(*reinterpret_cast<__half2*>(&r1.y));
            f2 = __half22float2(*reinterpret_cast<__half2*>(&r1.z));
            f3 = __half22float2(*reinterpret_cast<__half2*>(&r1.w));
            a0 += w1 * f0.x; a1 += w1 * f0.y; a2 += w1 * f1.x; a3 += w1 * f1.y;
            a4 += w1 * f2.x; a5 += w1 * f2.y; a6 += w1 * f3.x; a7 += w1 * f3.y;
        }
        for (; k < cnt; k += 8) {
            float w = s_w[hh][k];
            uint4 r0 = __ldg(&hrow4[(size_t)s_idx[k] * 32 + c8]);
            float2 f0 = __half22float2(*reinterpret_cast<__half2*>(&r0.x));
            float2 f1 = __half22float2(*reinterpret_cast<__half2*>(&r0.y));
            float2 f2 = __half22float2(*reinterpret_cast<__half2*>(&r0.z));
            float2 f3 = __half22float2(*reinterpret_cast<__half2*>(&r0.w));
            a0 += w * f0.x; a1 += w * f0.y; a2 += w * f1.x; a3 += w * f1.y;
            a4 += w * f2.x; a5 += w * f2.y; a6 += w * f3.x; a7 += w * f3.y;
        }
        int cb = c8 * 8;
        partF[q][cb + 0] = a0; partF[q][cb + 1] = a1; partF[q][cb + 2] = a2; partF[q][cb + 3] = a3;
        partF[q][cb + 4] = a4; partF[q][cb + 5] = a5; partF[q][cb + 6] = a6; partF[q][cb + 7] = a7;
        __syncthreads();
        // reduce 8 phases: thread = column (coalesced, conflict-free)
        {
            float v = partF[0][tid] + partF[1][tid] + partF[2][tid] + partF[3][tid]
                    + partF[4][tid] + partF[5][tid] + partF[6][tid] + partF[7][tid];
            s_x2[tid] = eluf(v / s_stat[tid >> 6]);
        }
    } else {
        // dense fallback (rare)
        int g = tid >> 6, l = tid & 63;
        const float* arow = adj + (size_t)row * NV;
        float s_i = g_s[g * NV + row];
        const float* tvec = g_t + g * NV;
        float mx = -INFINITY;
        for (int j = l; j < NV; j += 64) {
            float lv = lrelu(s_i + tvec[j]);
            if (arow[j] == 0.f) lv += NEGV;
            mx = fmaxf(mx, lv);
        }
        red[tid] = mx; __syncthreads();
        if (l < 32) {
            float m = fmaxf(red[tid], red[tid + 32]);
#pragma unroll
            for (int o = 16; o > 0; o >>= 1) m = fmaxf(m, __shfl_xor_sync(0xffffffffu, m, o));
            if (l == 0) s_stat[g] = m;
        }
        __syncthreads();
        mx = s_stat[g];
        float sum = 0.f;
        for (int j = l; j < NV; j += 64) {
            float lv = lrelu(s_i + tvec[j]);
            if (arow[j] == 0.f) lv += NEGV;
            sum += __expf(lv - mx);
        }
        __syncthreads();
        red[tid] = sum; __syncthreads();
        if (l < 32) {
            float s = red[tid] + red[tid + 32];
#pragma unroll
            for (int o = 16; o > 0; o >>= 1) s += __shfl_xor_sync(0xffffffffu, s, o);
            if (l == 0) s_stat[g] = s;
        }
        __syncthreads();
        float S = s_stat[g];
        float acc = 0.f;
        const __half* hb = g_Hh + g * 64 + l;
        for (int j = 0; j < NV; j++) {
            float lv = lrelu(s_i + tvec[j]);
            if (arow[j] == 0.f) lv += NEGV;
            acc += __expf(lv - mx) * __half2float(hb[(size_t)j * 256]);
        }
        s_x2[g * 64 + l] = eluf(acc / S);
    }
    __syncthreads();

    // ---- fused out-projection (Wout via L1) ----
    {
        int c = tid & 15, kq = tid >> 4;
        float acc = 0.f;
#pragma unroll
        for (int k = 0; k < 16; k++)
            acc += s_x2[kq * 16 + k] * __ldg(&Wout[(kq * 16 + k) * 16 + c]);
        part2[kq][c] = acc;
    }
    __syncthreads();
    if (tid < 16) {
        float h = 0.f;
#pragma unroll
        for (int w = 0; w < 16; w++) h += part2[w][tid];
        g_H2[(size_t)row * 16 + tid] = h;
        float sa = h * __ldg(&a1o[tid]), sb = h * __ldg(&a2o[tid]);
#pragma unroll
        for (int o = 8; o > 0; o >>= 1) {
            sa += __shfl_xor_sync(0xffffu, sa, o, 16);
            sb += __shfl_xor_sync(0xffffu, sb, o, 16);
        }
        if (tid == 0) { g_s2[row] = sa; g_t2[row] = sb; }
    }
}

// ---------------- K3: output attention, warp-per-row, float4 gather ----------------
__global__ void __launch_bounds__(128) k_attn_out(const float* __restrict__ adj, float* __restrict__ out) {
    __shared__ float s_w[4][CAP];
    __shared__ int   s_ix[4][CAP];
    __shared__ float part[4][8][16];
    int w = threadIdx.x >> 5, lane = threadIdx.x & 31;
    int row = blockIdx.x * 4 + w;
    int cnt = g_cnt[row];
    float s_i = g_s2[row];
    bool sparse = (cnt > 0 && cnt <= CAP);

    if (sparse) {
        const int* nb = g_nbr + (size_t)row * CAP;
        float mx = -INFINITY;
        for (int k = lane; k < cnt; k += 32) {
            int ix = __ldg(&nb[k]);
            s_ix[w][k] = ix;
            float lv = lrelu(s_i + __ldg(&g_t2[ix]));
            s_w[w][k] = lv;
            mx = fmaxf(mx, lv);
        }
#pragma unroll
        for (int o = 16; o > 0; o >>= 1) mx = fmaxf(mx, __shfl_xor_sync(0xffffffffu, mx, o));
        float sum = 0.f;
        for (int k = lane; k < cnt; k += 32) {
            float e = __expf(s_w[w][k] - mx);
            s_w[w][k] = e;
            sum += e;
        }
#pragma unroll
        for (int o = 16; o > 0; o >>= 1) sum += __shfl_xor_sync(0xffffffffu, sum, o);
        __syncwarp();
        // gather: 8 phases x 4 col-quads, float4 loads
        int ph = lane >> 2, c4 = lane & 3;
        const float4* h24 = reinterpret_cast<const float4*>(g_H2);
        float4 acc = make_float4(0.f, 0.f, 0.f, 0.f);
        int k = ph;
        for (; k + 8 < cnt; k += 16) {
            float w0 = s_w[w][k], w1 = s_w[w][k + 8];
            float4 v0 = __ldg(&h24[(size_t)s_ix[w][k] * 4 + c4]);
            float4 v1 = __ldg(&h24[(size_t)s_ix[w][k + 8] * 4 + c4]);
            acc.x += w0 * v0.x + w1 * v1.x;
            acc.y += w0 * v0.y + w1 * v1.y;
            acc.z += w0 * v0.z + w1 * v1.z;
            acc.w += w0 * v0.w + w1 * v1.w;
        }
        for (; k < cnt; k += 8) {
            float w0 = s_w[w][k];
            float4 v0 = __ldg(&h24[(size_t)s_ix[w][k] * 4 + c4]);
            acc.x += w0 * v0.x; acc.y += w0 * v0.y; acc.z += w0 * v0.z; acc.w += w0 * v0.w;
        }
        *reinterpret_cast<float4*>(&part[w][ph][c4 * 4]) = acc;
        __syncwarp();
        // lanes 0..15: reduce 8 phases, elu + class softmax
        float a = 0.f;
        if (lane < 16) {
#pragma unroll
            for (int p = 0; p < 8; p++) a += part[w][p][lane];
        }
        float v = eluf(a / sum);
        float m16 = v;
#pragma unroll
        for (int o = 8; o > 0; o >>= 1) m16 = fmaxf(m16, __shfl_xor_sync(0xffffffffu, m16, o, 16));
        float e = __expf(v - m16);
        float se = e;
#pragma unroll
        for (int o = 8; o > 0; o >>= 1) se += __shfl_xor_sync(0xffffffffu, se, o, 16);
        if (lane < 16) out[(size_t)row * 16 + lane] = e / se;
    } else {
        const float* arow = adj + (size_t)row * NV;
        float mx = -INFINITY;
        for (int j = lane; j < NV; j += 32) {
            float lv = lrelu(s_i + g_t2[j]);
            if (arow[j] == 0.f) lv += NEGV;
            mx = fmaxf(mx, lv);
        }
#pragma unroll
        for (int o = 16; o > 0; o >>= 1) mx = fmaxf(mx, __shfl_xor_sync(0xffffffffu, mx, o));
        float sum = 0.f;
        for (int j = lane; j < NV; j += 32) {
            float lv = lrelu(s_i + g_t2[j]);
            if (arow[j] == 0.f) lv += NEGV;
            sum += __expf(lv - mx);
        }
#pragma unroll
        for (int o = 16; o > 0; o >>= 1) sum += __shfl_xor_sync(0xffffffffu, sum, o);
        int q = lane >> 4, c = lane & 15;
        float acc = 0.f;
        for (int j = q; j < NV; j += 2) {
            float lv = lrelu(s_i + g_t2[j]);
            if (arow[j] == 0.f) lv += NEGV;
            acc += __expf(lv - mx) * __ldg(&g_H2[(size_t)j * 16 + c]);
        }
        acc += __shfl_down_sync(0xffffffffu, acc, 16);
        float v = eluf(acc / sum);
        float m16 = v;
#pragma unroll
        for (int o = 8; o > 0; o >>= 1) m16 = fmaxf(m16, __shfl_xor_sync(0xffffffffu, m16, o, 16));
        float e = __expf(v - m16);
        float se = e;
#pragma unroll
        for (int o = 8; o > 0; o >>= 1) se += __shfl_xor_sync(0xffffffffu, se, o, 16);
        if (lane < 16) out[(size_t)row * 16 + lane] = e / se;
    }
}

// ---------------- launch ----------------
extern "C" void kernel_launch(void* const* d_in, const int* in_sizes, int n_in,
                              void* d_out, int out_size) {
    const float* adj  = (const float*)d_in[0];
    const float* feat = (const float*)d_in[1];
    const float* W0   = (const float*)d_in[2];
    const float* a1_0 = (const float*)d_in[3];
    const float* a2_0 = (const float*)d_in[4];
    const float* Wout = (const float*)d_in[5];
    const float* a1o  = (const float*)d_in[6];
    const float* a2o  = (const float*)d_in[7];
    float* out = (float*)d_out;

    k_gemm<<<(NV / 64) * NHEAD, 256>>>(feat, W0, a1_0, a2_0);
    k_attn_hidden<<<NV, 256>>>(adj, Wout, a1o, a2o);
    k_attn_out<<<NV / 4, 128>>>(adj, out);
}

// round 15
// speedup vs baseline: 1.2424x; 1.0226x over previous
#include <cuda_runtime.h>
#include <cuda_fp16.h>
#include <mma.h>
#include <math.h>
#include <stdint.h>

using namespace nvcuda;

#define NV      6144
#define NFEAT   128
#define NHID    64
#define NHEAD   4
#define NCLASS  16
#define CAP     256
#define ALPHA   0.2f
#define NEGV    (-1e10f)
#define LDA     136
#define LDB     72

// ---------------- device scratch ----------------
__device__ __half g_featH[(size_t)NV * NFEAT];        // fp16 features
__device__ __half g_WeffH[NFEAT * NHEAD * NHID];      // fp16 folded weights [k][h*64+c]
__device__ __half g_Hh[(size_t)NV * NHEAD * NHID];
__device__ float  g_s[NHEAD * NV];
__device__ float  g_t[NHEAD * NV];
__device__ int    g_nbr[(size_t)NV * CAP];
__device__ int    g_cnt[NV];
__device__ float  g_H2[(size_t)NV * NCLASS];
__device__ float  g_s2[NV];
__device__ float  g_t2[NV];

__device__ __forceinline__ float lrelu(float x) { return x > 0.f ? x : ALPHA * x; }
__device__ __forceinline__ float eluf(float x)  { return x > 0.f ? x : (__expf(x) - 1.f); }

// ---------------- K0: prep — fold W0 -> fp16, convert feat -> fp16 ----------------
__global__ void __launch_bounds__(256) k_prep(const float* __restrict__ W0,
                                              const float* __restrict__ feat) {
    int b = blockIdx.x, tid = threadIdx.x;
    if (b < 128) {
        // Weff fold: 128 blocks x 256 outputs
        int linear = b * 256 + tid;
        int k = linear >> 8, C = linear & 255;
        int h = C >> 6, c = C & 63;
        const float* base = W0 + (size_t)h * 512 * 64;
        float v = 0.f;
#pragma unroll
        for (int t = 0; t < 4; t++) v += base[(t * 128 + k) * 64 + c];
        g_WeffH[k * 256 + C] = __float2half_rn(v);
    } else {
        // feat convert: 384 blocks x 2048 floats each
        int fb = b - 128;
        const float4* src = reinterpret_cast<const float4*>(feat) + (size_t)fb * 512 + tid * 2;
        float4 v0 = src[0], v1 = src[1];
        __half2 h0 = __floats2half2_rn(v0.x, v0.y);
        __half2 h1 = __floats2half2_rn(v0.z, v0.w);
        __half2 h2 = __floats2half2_rn(v1.x, v1.y);
        __half2 h3 = __floats2half2_rn(v1.z, v1.w);
        uint4 st;
        st.x = *reinterpret_cast<unsigned*>(&h0);
        st.y = *reinterpret_cast<unsigned*>(&h1);
        st.z = *reinterpret_cast<unsigned*>(&h2);
        st.w = *reinterpret_cast<unsigned*>(&h3);
        reinterpret_cast<uint4*>(g_featH)[(size_t)fb * 256 + tid] = st;
    }
}

// ---------------- K1: tensor-core GEMM (pure fp16 tile copies) + fused s/t ----------------
__global__ void __launch_bounds__(256) k_gemm(const float* __restrict__ a1g,
                                              const float* __restrict__ a2g) {
    __shared__ __align__(16) __half AsH[64 * LDA];
    __shared__ __align__(16) __half BsH[128 * LDB];
    float* Cs = reinterpret_cast<float*>(AsH);
    int tid = threadIdx.x;
    int head = blockIdx.x & 3;
    int row0 = (blockIdx.x >> 2) * 64;

    // A: 64x128 halfs = 1024 uint4 ; B: 128x64 halfs = 1024 uint4
    const uint4* fh4 = reinterpret_cast<const uint4*>(g_featH);
#pragma unroll
    for (int it = 0; it < 4; it++) {
        int idx = it * 256 + tid;
        int r = idx >> 4, c8 = idx & 15;   // 16 uint4 per 128-half row
        uint4 v = __ldg(&fh4[(size_t)(row0 + r) * 16 + c8]);
        *reinterpret_cast<uint4*>(&AsH[r * LDA + c8 * 8]) = v;
    }
#pragma unroll
    for (int it = 0; it < 4; it++) {
        int idx = it * 256 + tid;
        int k = idx >> 3, c8 = idx & 7;    // 8 uint4 per 64-half row
        uint4 v = *reinterpret_cast<const uint4*>(&g_WeffH[k * 256 + head * 64 + c8 * 8]);
        *reinterpret_cast<uint4*>(&BsH[k * LDB + c8 * 8]) = v;
    }
    __syncthreads();

    int warp = tid >> 5;
    int wr = (warp >> 1) * 16;
    int wc = (warp & 1) * 32;
    wmma::fragment<wmma::accumulator, 16, 16, 16, float> c0, c1;
    wmma::fill_fragment(c0, 0.f);
    wmma::fill_fragment(c1, 0.f);
#pragma unroll
    for (int k0 = 0; k0 < 128; k0 += 16) {
        wmma::fragment<wmma::matrix_a, 16, 16, 16, __half, wmma::row_major> a;
        wmma::fragment<wmma::matrix_b, 16, 16, 16, __half, wmma::row_major> b0, b1;
        wmma::load_matrix_sync(a, &AsH[wr * LDA + k0], LDA);
        wmma::load_matrix_sync(b0, &BsH[k0 * LDB + wc], LDB);
        wmma::load_matrix_sync(b1, &BsH[k0 * LDB + wc + 16], LDB);
        wmma::mma_sync(c0, a, b0, c0);
        wmma::mma_sync(c1, a, b1, c1);
    }
    __syncthreads();
    wmma::store_matrix_sync(&Cs[wr * 64 + wc], c0, 64, wmma::mem_row_major);
    wmma::store_matrix_sync(&Cs[wr * 64 + wc + 16], c1, 64, wmma::mem_row_major);
    __syncthreads();

    int r = tid >> 2, q = tid & 3;
    const float* crow = &Cs[r * 64 + q * 16];
    float sa = 0.f, sb = 0.f;
    __half hbuf[16];
#pragma unroll
    for (int c = 0; c < 16; c++) {
        float v = crow[c];
        hbuf[c] = __float2half_rn(v);
        sa += v * __ldg(&a1g[head * 64 + q * 16 + c]);
        sb += v * __ldg(&a2g[head * 64 + q * 16 + c]);
    }
    uint4* dst = reinterpret_cast<uint4*>(&g_Hh[(size_t)(row0 + r) * 256 + head * 64 + q * 16]);
    const uint4* src = reinterpret_cast<const uint4*>(hbuf);
    dst[0] = src[0];
    dst[1] = src[1];
    sa += __shfl_down_sync(0xffffffffu, sa, 2, 4);
    sa += __shfl_down_sync(0xffffffffu, sa, 1, 4);
    sb += __shfl_down_sync(0xffffffffu, sb, 2, 4);
    sb += __shfl_down_sync(0xffffffffu, sb, 1, 4);
    if (q == 0) {
        g_s[head * NV + row0 + r] = sa;
        g_t[head * NV + row0 + r] = sb;
    }
}

// ---------------- K2: FUSED adj-scan + hidden attention + out-proj ----------------
__global__ void __launch_bounds__(256) k_attn_hidden(const float* __restrict__ adj,
                                                     const float* __restrict__ Wout,
                                                     const float* __restrict__ a1o,
                                                     const float* __restrict__ a2o) {
    int row = blockIdx.x;
    int tid = threadIdx.x;
    int warp = tid >> 5, lane = tid & 31;
    __shared__ int    s_idx[CAP];
    __shared__ float  s_w[NHEAD][CAP];
    __shared__ float  s_stat[NHEAD];
    __shared__ float  partF[8][256];
    __shared__ float  s_x2[256];
    __shared__ float  part2[16][16];
    __shared__ float  red[256];
    __shared__ int    wsum[8];
    __shared__ int    s_cnt;

    // ---- phase 0: scan adj row, compact into smem ----
    {
        const uint4* a4 = reinterpret_cast<const uint4*>(adj) + (size_t)row * (NV / 4);
        uint4 v[6];
#pragma unroll
        for (int it = 0; it < 6; it++) v[it] = __ldg(&a4[it * 256 + tid]);
        unsigned mask = 0;
#pragma unroll
        for (int it = 0; it < 6; it++) {
            if (v[it].x) mask |= 1u << (it * 4 + 0);
            if (v[it].y) mask |= 1u << (it * 4 + 1);
            if (v[it].z) mask |= 1u << (it * 4 + 2);
            if (v[it].w) mask |= 1u << (it * 4 + 3);
        }
        int c = __popc(mask);
        int incl = c;
#pragma unroll
        for (int o = 1; o < 32; o <<= 1) {
            int n = __shfl_up_sync(0xffffffffu, incl, o);
            if (lane >= o) incl += n;
        }
        if (lane == 31) wsum[warp] = incl;
        __syncthreads();
        int base = 0;
#pragma unroll
        for (int w = 0; w < 8; w++) if (w < warp) base += wsum[w];
        int pos = base + incl - c;
        while (mask) {
            int b = __ffs(mask) - 1;
            mask &= mask - 1;
            if (pos < CAP) s_idx[pos] = (b >> 2) * 1024 + tid * 4 + (b & 3);
            pos++;
        }
        if (tid == 255) {
            int total = base + incl;
            s_cnt = total;
            g_cnt[row] = total;
        }
    }
    __syncthreads();
    int cnt = s_cnt;
    bool sparse = (cnt > 0 && cnt <= CAP);
    if (sparse)
        for (int k = tid; k < cnt; k += 256) g_nbr[(size_t)row * CAP + k] = s_idx[k];

    if (sparse) {
        if (warp < 4) {
            float s_i = g_s[warp * NV + row];
            const float* tv = g_t + warp * NV;
            float mx = -INFINITY;
            for (int k = lane; k < cnt; k += 32) {
                float lv = lrelu(s_i + __ldg(&tv[s_idx[k]]));
                s_w[warp][k] = lv;
                mx = fmaxf(mx, lv);
            }
#pragma unroll
            for (int o = 16; o > 0; o >>= 1) mx = fmaxf(mx, __shfl_xor_sync(0xffffffffu, mx, o));
            float sum = 0.f;
            for (int k = lane; k < cnt; k += 32) {
                float e = __expf(s_w[warp][k] - mx);
                s_w[warp][k] = e;
                sum += e;
            }
#pragma unroll
            for (int o = 16; o > 0; o >>= 1) sum += __shfl_xor_sync(0xffffffffu, sum, o);
            if (lane == 0) s_stat[warp] = sum;
        }
        __syncthreads();
        int q = tid >> 5;
        int c8 = lane;
        int hh = c8 >> 3;
        float a0 = 0.f, a1 = 0.f, a2 = 0.f, a3 = 0.f, a4 = 0.f, a5 = 0.f, a6 = 0.f, a7 = 0.f;
        const uint4* hrow4 = reinterpret_cast<const uint4*>(g_Hh);
        int k = q;
        for (; k + 8 < cnt; k += 16) {
            float w0 = s_w[hh][k], w1 = s_w[hh][k + 8];
            uint4 r0 = __ldg(&hrow4[(size_t)s_idx[k] * 32 + c8]);
            uint4 r1 = __ldg(&hrow4[(size_t)s_idx[k + 8] * 32 + c8]);
            float2 f0 = __half22float2(*reinterpret_cast<__half2*>(&r0.x));
            float2 f1 = __half22float2(*reinterpret_cast<__half2*>(&r0.y));
            float2 f2 = __half22float2(*reinterpret_cast<__half2*>(&r0.z));
            float2 f3 = __half22float2(*reinterpret_cast<__half2*>(&r0.w));
            a0 += w0 * f0.x; a1 += w0 * f0.y; a2 += w0 * f1.x; a3 += w0 * f1.y;
            a4 += w0 * f2.x; a5 += w0 * f2.y; a6 += w0 * f3.x; a7 += w0 * f3.y;
            f0 = __half22float2(*reinterpret_cast<__half2*>(&r1.x));
            f1 = __half22float2(*reinterpret_cast<__half2*>(&r1.y));
            f2 = __half22float2(*reinterpret_cast<__half2*>(&r1.z));
            f3 = __half22float2(*reinterpret_cast<__half2*>(&r1.w));
            a0 += w1 * f0.x; a1 += w1 * f0.y; a2 += w1 * f1.x; a3 += w1 * f1.y;
            a4 += w1 * f2.x; a5 += w1 * f2.y; a6 += w1 * f3.x; a7 += w1 * f3.y;
        }
        for (; k < cnt; k += 8) {
            float w = s_w[hh][k];
            uint4 r0 = __ldg(&hrow4[(size_t)s_idx[k] * 32 + c8]);
            float2 f0 = __half22float2(*reinterpret_cast<__half2*>(&r0.x));
            float2 f1 = __half22float2(*reinterpret_cast<__half2*>(&r0.y));
            float2 f2 = __half22float2(*reinterpret_cast<__half2*>(&r0.z));
            float2 f3 = __half22float2(*reinterpret_cast<__half2*>(&r0.w));
            a0 += w * f0.x; a1 += w * f0.y; a2 += w * f1.x; a3 += w * f1.y;
            a4 += w * f2.x; a5 += w * f2.y; a6 += w * f3.x; a7 += w * f3.y;
        }
        int cb = c8 * 8;
        partF[q][cb + 0] = a0; partF[q][cb + 1] = a1; partF[q][cb + 2] = a2; partF[q][cb + 3] = a3;
        partF[q][cb + 4] = a4; partF[q][cb + 5] = a5; partF[q][cb + 6] = a6; partF[q][cb + 7] = a7;
        __syncthreads();
        {
            float v = partF[0][tid] + partF[1][tid] + partF[2][tid] + partF[3][tid]
                    + partF[4][tid] + partF[5][tid] + partF[6][tid] + partF[7][tid];
            s_x2[tid] = eluf(v / s_stat[tid >> 6]);
        }
    } else {
        int g = tid >> 6, l = tid & 63;
        const float* arow = adj + (size_t)row * NV;
        float s_i = g_s[g * NV + row];
        const float* tvec = g_t + g * NV;
        float mx = -INFINITY;
        for (int j = l; j < NV; j += 64) {
            float lv = lrelu(s_i + tvec[j]);
            if (arow[j] == 0.f) lv += NEGV;
            mx = fmaxf(mx, lv);
        }
        red[tid] = mx; __syncthreads();
        if (l < 32) {
            float m = fmaxf(red[tid], red[tid + 32]);
#pragma unroll
            for (int o = 16; o > 0; o >>= 1) m = fmaxf(m, __shfl_xor_sync(0xffffffffu, m, o));
            if (l == 0) s_stat[g] = m;
        }
        __syncthreads();
        mx = s_stat[g];
        float sum = 0.f;
        for (int j = l; j < NV; j += 64) {
            float lv = lrelu(s_i + tvec[j]);
            if (arow[j] == 0.f) lv += NEGV;
            sum += __expf(lv - mx);
        }
        __syncthreads();
        red[tid] = sum; __syncthreads();
        if (l < 32) {
            float s = red[tid] + red[tid + 32];
#pragma unroll
            for (int o = 16; o > 0; o >>= 1) s += __shfl_xor_sync(0xffffffffu, s, o);
            if (l == 0) s_stat[g] = s;
        }
        __syncthreads();
        float S = s_stat[g];
        float acc = 0.f;
        const __half* hb = g_Hh + g * 64 + l;
        for (int j = 0; j < NV; j++) {
            float lv = lrelu(s_i + tvec[j]);
            if (arow[j] == 0.f) lv += NEGV;
            acc += __expf(lv - mx) * __half2float(hb[(size_t)j * 256]);
        }
        s_x2[g * 64 + l] = eluf(acc / S);
    }
    __syncthreads();

    // ---- fused out-projection (Wout via L1) ----
    {
        int c = tid & 15, kq = tid >> 4;
        float acc = 0.f;
#pragma unroll
        for (int k = 0; k < 16; k++)
            acc += s_x2[kq * 16 + k] * __ldg(&Wout[(kq * 16 + k) * 16 + c]);
        part2[kq][c] = acc;
    }
    __syncthreads();
    if (tid < 16) {
        float h = 0.f;
#pragma unroll
        for (int w = 0; w < 16; w++) h += part2[w][tid];
        g_H2[(size_t)row * 16 + tid] = h;
        float sa = h * __ldg(&a1o[tid]), sb = h * __ldg(&a2o[tid]);
#pragma unroll
        for (int o = 8; o > 0; o >>= 1) {
            sa += __shfl_xor_sync(0xffffu, sa, o, 16);
            sb += __shfl_xor_sync(0xffffu, sb, o, 16);
        }
        if (tid == 0) { g_s2[row] = sa; g_t2[row] = sb; }
    }
}

// ---------------- K3: output attention, warp-per-row, float4 gather ----------------
__global__ void __launch_bounds__(128) k_attn_out(const float* __restrict__ adj, float* __restrict__ out) {
    __shared__ float s_w[4][CAP];
    __shared__ int   s_ix[4][CAP];
    __shared__ float part[4][8][16];
    int w = threadIdx.x >> 5, lane = threadIdx.x & 31;
    int row = blockIdx.x * 4 + w;
    int cnt = g_cnt[row];
    float s_i = g_s2[row];
    bool sparse = (cnt > 0 && cnt <= CAP);

    if (sparse) {
        const int* nb = g_nbr + (size_t)row * CAP;
        float mx = -INFINITY;
        for (int k = lane; k < cnt; k += 32) {
            int ix = __ldg(&nb[k]);
            s_ix[w][k] = ix;
            float lv = lrelu(s_i + __ldg(&g_t2[ix]));
            s_w[w][k] = lv;
            mx = fmaxf(mx, lv);
        }
#pragma unroll
        for (int o = 16; o > 0; o >>= 1) mx = fmaxf(mx, __shfl_xor_sync(0xffffffffu, mx, o));
        float sum = 0.f;
        for (int k = lane; k < cnt; k += 32) {
            float e = __expf(s_w[w][k] - mx);
            s_w[w][k] = e;
            sum += e;
        }
#pragma unroll
        for (int o = 16; o > 0; o >>= 1) sum += __shfl_xor_sync(0xffffffffu, sum, o);
        __syncwarp();
        int ph = lane >> 2, c4 = lane & 3;
        const float4* h24 = reinterpret_cast<const float4*>(g_H2);
        float4 acc = make_float4(0.f, 0.f, 0.f, 0.f);
        int k = ph;
        for (; k + 8 < cnt; k += 16) {
            float w0 = s_w[w][k], w1 = s_w[w][k + 8];
            float4 v0 = __ldg(&h24[(size_t)s_ix[w][k] * 4 + c4]);
            float4 v1 = __ldg(&h24[(size_t)s_ix[w][k + 8] * 4 + c4]);
            acc.x += w0 * v0.x + w1 * v1.x;
            acc.y += w0 * v0.y + w1 * v1.y;
            acc.z += w0 * v0.z + w1 * v1.z;
            acc.w += w0 * v0.w + w1 * v1.w;
        }
        for (; k < cnt; k += 8) {
            float w0 = s_w[w][k];
            float4 v0 = __ldg(&h24[(size_t)s_ix[w][k] * 4 + c4]);
            acc.x += w0 * v0.x; acc.y += w0 * v0.y; acc.z += w0 * v0.z; acc.w += w0 * v0.w;
        }
        *reinterpret_cast<float4*>(&part[w][ph][c4 * 4]) = acc;
        __syncwarp();
        float a = 0.f;
        if (lane < 16) {
#pragma unroll
            for (int p = 0; p < 8; p++) a += part[w][p][lane];
        }
        float v = eluf(a / sum);
        float m16 = v;
#pragma unroll
        for (int o = 8; o > 0; o >>= 1) m16 = fmaxf(m16, __shfl_xor_sync(0xffffffffu, m16, o, 16));
        float e = __expf(v - m16);
        float se = e;
#pragma unroll
        for (int o = 8; o > 0; o >>= 1) se += __shfl_xor_sync(0xffffffffu, se, o, 16);
        if (lane < 16) out[(size_t)row * 16 + lane] = e / se;
    } else {
        const float* arow = adj + (size_t)row * NV;
        float mx = -INFINITY;
        for (int j = lane; j < NV; j += 32) {
            float lv = lrelu(s_i + g_t2[j]);
            if (arow[j] == 0.f) lv += NEGV;
            mx = fmaxf(mx, lv);
        }
#pragma unroll
        for (int o = 16; o > 0; o >>= 1) mx = fmaxf(mx, __shfl_xor_sync(0xffffffffu, mx, o));
        float sum = 0.f;
        for (int j = lane; j < NV; j += 32) {
            float lv = lrelu(s_i + g_t2[j]);
            if (arow[j] == 0.f) lv += NEGV;
            sum += __expf(lv - mx);
        }
#pragma unroll
        for (int o = 16; o > 0; o >>= 1) sum += __shfl_xor_sync(0xffffffffu, sum, o);
        int q = lane >> 4, c = lane & 15;
        float acc = 0.f;
        for (int j = q; j < NV; j += 2) {
            float lv = lrelu(s_i + g_t2[j]);
            if (arow[j] == 0.f) lv += NEGV;
            acc += __expf(lv - mx) * __ldg(&g_H2[(size_t)j * 16 + c]);
        }
        acc += __shfl_down_sync(0xffffffffu, acc, 16);
        float v = eluf(acc / sum);
        float m16 = v;
#pragma unroll
        for (int o = 8; o > 0; o >>= 1) m16 = fmaxf(m16, __shfl_xor_sync(0xffffffffu, m16, o, 16));
        float e = __expf(v - m16);
        float se = e;
#pragma unroll
        for (int o = 8; o > 0; o >>= 1) se += __shfl_xor_sync(0xffffffffu, se, o, 16);
        if (lane < 16) out[(size_t)row * 16 + lane] = e / se;
    }
}

// ---------------- launch ----------------
extern "C" void kernel_launch(void* const* d_in, const int* in_sizes, int n_in,
                              void* d_out, int out_size) {
    const float* adj  = (const float*)d_in[0];
    const float* feat = (const float*)d_in[1];
    const float* W0   = (const float*)d_in[2];
    const float* a1_0 = (const float*)d_in[3];
    const float* a2_0 = (const float*)d_in[4];
    const float* Wout = (const float*)d_in[5];
    const float* a1o  = (const float*)d_in[6];
    const float* a2o  = (const float*)d_in[7];
    float* out = (float*)d_out;

    k_prep<<<512, 256>>>(W0, feat);                       // fold W0 + feat->fp16 (~1.5us)
    k_gemm<<<(NV / 64) * NHEAD, 256>>>(a1_0, a2_0);       // pure fp16 tile copies + wmma
    k_attn_hidden<<<NV, 256>>>(adj, Wout, a1o, a2o);
    k_attn_out<<<NV / 4, 128>>>(adj, out);
}

// round 16
// speedup vs baseline: 1.2479x; 1.0044x over previous
#include <cuda_runtime.h>
#include <cuda_fp16.h>
#include <mma.h>
#include <math.h>
#include <stdint.h>

using namespace nvcuda;

#define NV      6144
#define NFEAT   128
#define NHID    64
#define NHEAD   4
#define NCLASS  16
#define CAP     256
#define ALPHA   0.2f
#define NEGV    (-1e10f)
#define LDA     136
#define LDB     72
#define ROWS_PER_OUT_BLOCK 8

// ---------------- device scratch ----------------
__device__ __half g_featH[(size_t)NV * NFEAT];
__device__ __half g_WeffH[NFEAT * NHEAD * NHID];
__device__ __half g_Hh[(size_t)NV * NHEAD * NHID];
__device__ float  g_s[NHEAD * NV];
__device__ float  g_t[NHEAD * NV];
__device__ int    g_nbr[(size_t)NV * CAP];
__device__ int    g_cnt[NV];
__device__ float  g_H2[(size_t)NV * NCLASS];
__device__ float  g_s2[NV];
__device__ float  g_t2[NV];

__device__ __forceinline__ float lrelu(float x) { return x > 0.f ? x : ALPHA * x; }
__device__ __forceinline__ float eluf(float x)  { return x > 0.f ? x : (__expf(x) - 1.f); }

// ---------------- K0: prep — fold W0 -> fp16, convert feat -> fp16 ----------------
__global__ void __launch_bounds__(256) k_prep(const float* __restrict__ W0,
                                              const float* __restrict__ feat) {
    int b = blockIdx.x, tid = threadIdx.x;
    if (b < 128) {
        int linear = b * 256 + tid;
        int k = linear >> 8, C = linear & 255;
        int h = C >> 6, c = C & 63;
        const float* base = W0 + (size_t)h * 512 * 64;
        float v = 0.f;
#pragma unroll
        for (int t = 0; t < 4; t++) v += base[(t * 128 + k) * 64 + c];
        g_WeffH[k * 256 + C] = __float2half_rn(v);
    } else {
        int fb = b - 128;
        const float4* src = reinterpret_cast<const float4*>(feat) + (size_t)fb * 512 + tid * 2;
        float4 v0 = src[0], v1 = src[1];
        __half2 h0 = __floats2half2_rn(v0.x, v0.y);
        __half2 h1 = __floats2half2_rn(v0.z, v0.w);
        __half2 h2 = __floats2half2_rn(v1.x, v1.y);
        __half2 h3 = __floats2half2_rn(v1.z, v1.w);
        uint4 st;
        st.x = *reinterpret_cast<unsigned*>(&h0);
        st.y = *reinterpret_cast<unsigned*>(&h1);
        st.z = *reinterpret_cast<unsigned*>(&h2);
        st.w = *reinterpret_cast<unsigned*>(&h3);
        reinterpret_cast<uint4*>(g_featH)[(size_t)fb * 256 + tid] = st;
    }
}

// ---------------- K1: tensor-core GEMM + fused s/t ----------------
__global__ void __launch_bounds__(256) k_gemm(const float* __restrict__ a1g,
                                              const float* __restrict__ a2g) {
    __shared__ __align__(16) __half AsH[64 * LDA];
    __shared__ __align__(16) __half BsH[128 * LDB];
    float* Cs = reinterpret_cast<float*>(AsH);
    int tid = threadIdx.x;
    int head = blockIdx.x & 3;
    int row0 = (blockIdx.x >> 2) * 64;

    const uint4* fh4 = reinterpret_cast<const uint4*>(g_featH);
#pragma unroll
    for (int it = 0; it < 4; it++) {
        int idx = it * 256 + tid;
        int r = idx >> 4, c8 = idx & 15;
        uint4 v = __ldg(&fh4[(size_t)(row0 + r) * 16 + c8]);
        *reinterpret_cast<uint4*>(&AsH[r * LDA + c8 * 8]) = v;
    }
#pragma unroll
    for (int it = 0; it < 4; it++) {
        int idx = it * 256 + tid;
        int k = idx >> 3, c8 = idx & 7;
        uint4 v = *reinterpret_cast<const uint4*>(&g_WeffH[k * 256 + head * 64 + c8 * 8]);
        *reinterpret_cast<uint4*>(&BsH[k * LDB + c8 * 8]) = v;
    }
    __syncthreads();

    int warp = tid >> 5;
    int wr = (warp >> 1) * 16;
    int wc = (warp & 1) * 32;
    wmma::fragment<wmma::accumulator, 16, 16, 16, float> c0, c1;
    wmma::fill_fragment(c0, 0.f);
    wmma::fill_fragment(c1, 0.f);
#pragma unroll
    for (int k0 = 0; k0 < 128; k0 += 16) {
        wmma::fragment<wmma::matrix_a, 16, 16, 16, __half, wmma::row_major> a;
        wmma::fragment<wmma::matrix_b, 16, 16, 16, __half, wmma::row_major> b0, b1;
        wmma::load_matrix_sync(a, &AsH[wr * LDA + k0], LDA);
        wmma::load_matrix_sync(b0, &BsH[k0 * LDB + wc], LDB);
        wmma::load_matrix_sync(b1, &BsH[k0 * LDB + wc + 16], LDB);
        wmma::mma_sync(c0, a, b0, c0);
        wmma::mma_sync(c1, a, b1, c1);
    }
    __syncthreads();
    wmma::store_matrix_sync(&Cs[wr * 64 + wc], c0, 64, wmma::mem_row_major);
    wmma::store_matrix_sync(&Cs[wr * 64 + wc + 16], c1, 64, wmma::mem_row_major);
    __syncthreads();

    int r = tid >> 2, q = tid & 3;
    const float* crow = &Cs[r * 64 + q * 16];
    float sa = 0.f, sb = 0.f;
    __half hbuf[16];
#pragma unroll
    for (int c = 0; c < 16; c++) {
        float v = crow[c];
        hbuf[c] = __float2half_rn(v);
        sa += v * __ldg(&a1g[head * 64 + q * 16 + c]);
        sb += v * __ldg(&a2g[head * 64 + q * 16 + c]);
    }
    uint4* dst = reinterpret_cast<uint4*>(&g_Hh[(size_t)(row0 + r) * 256 + head * 64 + q * 16]);
    const uint4* src = reinterpret_cast<const uint4*>(hbuf);
    dst[0] = src[0];
    dst[1] = src[1];
    sa += __shfl_down_sync(0xffffffffu, sa, 2, 4);
    sa += __shfl_down_sync(0xffffffffu, sa, 1, 4);
    sb += __shfl_down_sync(0xffffffffu, sb, 2, 4);
    sb += __shfl_down_sync(0xffffffffu, sb, 1, 4);
    if (q == 0) {
        g_s[head * NV + row0 + r] = sa;
        g_t[head * NV + row0 + r] = sb;
    }
}

// ---------------- K2: FUSED adj-scan (streaming loads) + hidden attention + out-proj ----------------
__global__ void __launch_bounds__(256) k_attn_hidden(const float* __restrict__ adj,
                                                     const float* __restrict__ Wout,
                                                     const float* __restrict__ a1o,
                                                     const float* __restrict__ a2o) {
    int row = blockIdx.x;
    int tid = threadIdx.x;
    int warp = tid >> 5, lane = tid & 31;
    __shared__ int    s_idx[CAP];
    __shared__ float  s_w[NHEAD][CAP];
    __shared__ float  s_stat[NHEAD];
    __shared__ float  partF[8][256];
    __shared__ float  s_x2[256];
    __shared__ float  part2[16][16];
    __shared__ float  red[256];
    __shared__ int    wsum[8];
    __shared__ int    s_cnt;

    // ---- phase 0: streaming scan of adj row (evict-first: don't pollute L2) ----
    {
        const uint4* a4 = reinterpret_cast<const uint4*>(adj) + (size_t)row * (NV / 4);
        uint4 v[6];
#pragma unroll
        for (int it = 0; it < 6; it++) v[it] = __ldcs(&a4[it * 256 + tid]);
        unsigned mask = 0;
#pragma unroll
        for (int it = 0; it < 6; it++) {
            if (v[it].x) mask |= 1u << (it * 4 + 0);
            if (v[it].y) mask |= 1u << (it * 4 + 1);
            if (v[it].z) mask |= 1u << (it * 4 + 2);
            if (v[it].w) mask |= 1u << (it * 4 + 3);
        }
        int c = __popc(mask);
        int incl = c;
#pragma unroll
        for (int o = 1; o < 32; o <<= 1) {
            int n = __shfl_up_sync(0xffffffffu, incl, o);
            if (lane >= o) incl += n;
        }
        if (lane == 31) wsum[warp] = incl;
        __syncthreads();
        int base = 0;
#pragma unroll
        for (int w = 0; w < 8; w++) if (w < warp) base += wsum[w];
        int pos = base + incl - c;
        while (mask) {
            int b = __ffs(mask) - 1;
            mask &= mask - 1;
            if (pos < CAP) s_idx[pos] = (b >> 2) * 1024 + tid * 4 + (b & 3);
            pos++;
        }
        if (tid == 255) {
            int total = base + incl;
            s_cnt = total;
            g_cnt[row] = total;
        }
    }
    __syncthreads();
    int cnt = s_cnt;
    bool sparse = (cnt > 0 && cnt <= CAP);
    if (sparse)
        for (int k = tid; k < cnt; k += 256) g_nbr[(size_t)row * CAP + k] = s_idx[k];

    if (sparse) {
        if (warp < 4) {
            float s_i = g_s[warp * NV + row];
            const float* tv = g_t + warp * NV;
            float mx = -INFINITY;
            for (int k = lane; k < cnt; k += 32) {
                float lv = lrelu(s_i + __ldg(&tv[s_idx[k]]));
                s_w[warp][k] = lv;
                mx = fmaxf(mx, lv);
            }
#pragma unroll
            for (int o = 16; o > 0; o >>= 1) mx = fmaxf(mx, __shfl_xor_sync(0xffffffffu, mx, o));
            float sum = 0.f;
            for (int k = lane; k < cnt; k += 32) {
                float e = __expf(s_w[warp][k] - mx);
                s_w[warp][k] = e;
                sum += e;
            }
#pragma unroll
            for (int o = 16; o > 0; o >>= 1) sum += __shfl_xor_sync(0xffffffffu, sum, o);
            if (lane == 0) s_stat[warp] = sum;
        }
        __syncthreads();
        int q = tid >> 5;
        int c8 = lane;
        int hh = c8 >> 3;
        float a0 = 0.f, a1 = 0.f, a2 = 0.f, a3 = 0.f, a4 = 0.f, a5 = 0.f, a6 = 0.f, a7 = 0.f;
        const uint4* hrow4 = reinterpret_cast<const uint4*>(g_Hh);
        int k = q;
        for (; k + 8 < cnt; k += 16) {
            float w0 = s_w[hh][k], w1 = s_w[hh][k + 8];
            uint4 r0 = __ldg(&hrow4[(size_t)s_idx[k] * 32 + c8]);
            uint4 r1 = __ldg(&hrow4[(size_t)s_idx[k + 8] * 32 + c8]);
            float2 f0 = __half22float2(*reinterpret_cast<__half2*>(&r0.x));
            float2 f1 = __half22float2(*reinterpret_cast<__half2*>(&r0.y));
            float2 f2 = __half22float2(*reinterpret_cast<__half2*>(&r0.z));
            float2 f3 = __half22float2(*reinterpret_cast<__half2*>(&r0.w));
            a0 += w0 * f0.x; a1 += w0 * f0.y; a2 += w0 * f1.x; a3 += w0 * f1.y;
            a4 += w0 * f2.x; a5 += w0 * f2.y; a6 += w0 * f3.x; a7 += w0 * f3.y;
            f0 = __half22float2(*reinterpret_cast<__half2*>(&r1.x));
            f1 = __half22float2(*reinterpret_cast<__half2*>(&r1.y));
            f2 = __half22float2(*reinterpret_cast<__half2*>(&r1.z));
            f3 = __half22float2(*reinterpret_cast<__half2*>(&r1.w));
            a0 += w1 * f0.x; a1 += w1 * f0.y; a2 += w1 * f1.x; a3 += w1 * f1.y;
            a4 += w1 * f2.x; a5 += w1 * f2.y; a6 += w1 * f3.x; a7 += w1 * f3.y;
        }
        for (; k < cnt; k += 8) {
            float w = s_w[hh][k];
            uint4 r0 = __ldg(&hrow4[(size_t)s_idx[k] * 32 + c8]);
            float2 f0 = __half22float2(*reinterpret_cast<__half2*>(&r0.x));
            float2 f1 = __half22float2(*reinterpret_cast<__half2*>(&r0.y));
            float2 f2 = __half22float2(*reinterpret_cast<__half2*>(&r0.z));
            float2 f3 = __half22float2(*reinterpret_cast<__half2*>(&r0.w));
            a0 += w * f0.x; a1 += w * f0.y; a2 += w * f1.x; a3 += w * f1.y;
            a4 += w * f2.x; a5 += w * f2.y; a6 += w * f3.x; a7 += w * f3.y;
        }
        int cb = c8 * 8;
        partF[q][cb + 0] = a0; partF[q][cb + 1] = a1; partF[q][cb + 2] = a2; partF[q][cb + 3] = a3;
        partF[q][cb + 4] = a4; partF[q][cb + 5] = a5; partF[q][cb + 6] = a6; partF[q][cb + 7] = a7;
        __syncthreads();
        {
            float v = partF[0][tid] + partF[1][tid] + partF[2][tid] + partF[3][tid]
                    + partF[4][tid] + partF[5][tid] + partF[6][tid] + partF[7][tid];
            s_x2[tid] = eluf(v / s_stat[tid >> 6]);
        }
    } else {
        int g = tid >> 6, l = tid & 63;
        const float* arow = adj + (size_t)row * NV;
        float s_i = g_s[g * NV + row];
        const float* tvec = g_t + g * NV;
        float mx = -INFINITY;
        for (int j = l; j < NV; j += 64) {
            float lv = lrelu(s_i + tvec[j]);
            if (__ldcs(&arow[j]) == 0.f) lv += NEGV;
            mx = fmaxf(mx, lv);
        }
        red[tid] = mx; __syncthreads();
        if (l < 32) {
            float m = fmaxf(red[tid], red[tid + 32]);
#pragma unroll
            for (int o = 16; o > 0; o >>= 1) m = fmaxf(m, __shfl_xor_sync(0xffffffffu, m, o));
            if (l == 0) s_stat[g] = m;
        }
        __syncthreads();
        mx = s_stat[g];
        float sum = 0.f;
        for (int j = l; j < NV; j += 64) {
            float lv = lrelu(s_i + tvec[j]);
            if (__ldcs(&arow[j]) == 0.f) lv += NEGV;
            sum += __expf(lv - mx);
        }
        __syncthreads();
        red[tid] = sum; __syncthreads();
        if (l < 32) {
            float s = red[tid] + red[tid + 32];
#pragma unroll
            for (int o = 16; o > 0; o >>= 1) s += __shfl_xor_sync(0xffffffffu, s, o);
            if (l == 0) s_stat[g] = s;
        }
        __syncthreads();
        float S = s_stat[g];
        float acc = 0.f;
        const __half* hb = g_Hh + g * 64 + l;
        for (int j = 0; j < NV; j++) {
            float lv = lrelu(s_i + tvec[j]);
            if (arow[j] == 0.f) lv += NEGV;
            acc += __expf(lv - mx) * __half2float(hb[(size_t)j * 256]);
        }
        s_x2[g * 64 + l] = eluf(acc / S);
    }
    __syncthreads();

    // ---- fused out-projection ----
    {
        int c = tid & 15, kq = tid >> 4;
        float acc = 0.f;
#pragma unroll
        for (int k = 0; k < 16; k++)
            acc += s_x2[kq * 16 + k] * __ldg(&Wout[(kq * 16 + k) * 16 + c]);
        part2[kq][c] = acc;
    }
    __syncthreads();
    if (tid < 16) {
        float h = 0.f;
#pragma unroll
        for (int w = 0; w < 16; w++) h += part2[w][tid];
        g_H2[(size_t)row * 16 + tid] = h;
        float sa = h * __ldg(&a1o[tid]), sb = h * __ldg(&a2o[tid]);
#pragma unroll
        for (int o = 8; o > 0; o >>= 1) {
            sa += __shfl_xor_sync(0xffffu, sa, o, 16);
            sb += __shfl_xor_sync(0xffffu, sb, o, 16);
        }
        if (tid == 0) { g_s2[row] = sa; g_t2[row] = sb; }
    }
}

// ---------------- K3: output attention, warp-per-row, 8 rows/block ----------------
__global__ void __launch_bounds__(256) k_attn_out(const float* __restrict__ adj, float* __restrict__ out) {
    __shared__ float s_w[ROWS_PER_OUT_BLOCK][CAP];
    __shared__ int   s_ix[ROWS_PER_OUT_BLOCK][CAP];
    __shared__ float part[ROWS_PER_OUT_BLOCK][8][16];
    int w = threadIdx.x >> 5, lane = threadIdx.x & 31;
    int row = blockIdx.x * ROWS_PER_OUT_BLOCK + w;
    int cnt = g_cnt[row];
    float s_i = g_s2[row];
    bool sparse = (cnt > 0 && cnt <= CAP);

    if (sparse) {
        const int* nb = g_nbr + (size_t)row * CAP;
        float mx = -INFINITY;
        for (int k = lane; k < cnt; k += 32) {
            int ix = __ldg(&nb[k]);
            s_ix[w][k] = ix;
            float lv = lrelu(s_i + __ldg(&g_t2[ix]));
            s_w[w][k] = lv;
            mx = fmaxf(mx, lv);
        }
#pragma unroll
        for (int o = 16; o > 0; o >>= 1) mx = fmaxf(mx, __shfl_xor_sync(0xffffffffu, mx, o));
        float sum = 0.f;
        for (int k = lane; k < cnt; k += 32) {
            float e = __expf(s_w[w][k] - mx);
            s_w[w][k] = e;
            sum += e;
        }
#pragma unroll
        for (int o = 16; o > 0; o >>= 1) sum += __shfl_xor_sync(0xffffffffu, sum, o);
        __syncwarp();
        int ph = lane >> 2, c4 = lane & 3;
        const float4* h24 = reinterpret_cast<const float4*>(g_H2);
        float4 acc = make_float4(0.f, 0.f, 0.f, 0.f);
        int k = ph;
        for (; k + 8 < cnt; k += 16) {
            float w0 = s_w[w][k], w1 = s_w[w][k + 8];
            float4 v0 = __ldg(&h24[(size_t)s_ix[w][k] * 4 + c4]);
            float4 v1 = __ldg(&h24[(size_t)s_ix[w][k + 8] * 4 + c4]);
            acc.x += w0 * v0.x + w1 * v1.x;
            acc.y += w0 * v0.y + w1 * v1.y;
            acc.z += w0 * v0.z + w1 * v1.z;
            acc.w += w0 * v0.w + w1 * v1.w;
        }
        for (; k < cnt; k += 8) {
            float w0 = s_w[w][k];
            float4 v0 = __ldg(&h24[(size_t)s_ix[w][k] * 4 + c4]);
            acc.x += w0 * v0.x; acc.y += w0 * v0.y; acc.z += w0 * v0.z; acc.w += w0 * v0.w;
        }
        *reinterpret_cast<float4*>(&part[w][ph][c4 * 4]) = acc;
        __syncwarp();
        float a = 0.f;
        if (lane < 16) {
#pragma unroll
            for (int p = 0; p < 8; p++) a += part[w][p][lane];
        }
        float v = eluf(a / sum);
        float m16 = v;
#pragma unroll
        for (int o = 8; o > 0; o >>= 1) m16 = fmaxf(m16, __shfl_xor_sync(0xffffffffu, m16, o, 16));
        float e = __expf(v - m16);
        float se = e;
#pragma unroll
        for (int o = 8; o > 0; o >>= 1) se += __shfl_xor_sync(0xffffffffu, se, o, 16);
        if (lane < 16) out[(size_t)row * 16 + lane] = e / se;
    } else {
        const float* arow = adj + (size_t)row * NV;
        float mx = -INFINITY;
        for (int j = lane; j < NV; j += 32) {
            float lv = lrelu(s_i + g_t2[j]);
            if (__ldcs(&arow[j]) == 0.f) lv += NEGV;
            mx = fmaxf(mx, lv);
        }
#pragma unroll
        for (int o = 16; o > 0; o >>= 1) mx = fmaxf(mx, __shfl_xor_sync(0xffffffffu, mx, o));
        float sum = 0.f;
        for (int j = lane; j < NV; j += 32) {
            float lv = lrelu(s_i + g_t2[j]);
            if (__ldcs(&arow[j]) == 0.f) lv += NEGV;
            sum += __expf(lv - mx);
        }
#pragma unroll
        for (int o = 16; o > 0; o >>= 1) sum += __shfl_xor_sync(0xffffffffu, sum, o);
        int q = lane >> 4, c = lane & 15;
        float acc = 0.f;
        for (int j = q; j < NV; j += 2) {
            float lv = lrelu(s_i + g_t2[j]);
            if (arow[j] == 0.f) lv += NEGV;
            acc += __expf(lv - mx) * __ldg(&g_H2[(size_t)j * 16 + c]);
        }
        acc += __shfl_down_sync(0xffffffffu, acc, 16);
        float v = eluf(acc / sum);
        float m16 = v;
#pragma unroll
        for (int o = 8; o > 0; o >>= 1) m16 = fmaxf(m16, __shfl_xor_sync(0xffffffffu, m16, o, 16));
        float e = __expf(v - m16);
        float se = e;
#pragma unroll
        for (int o = 8; o > 0; o >>= 1) se += __shfl_xor_sync(0xffffffffu, se, o, 16);
        if (lane < 16) out[(size_t)row * 16 + lane] = e / se;
    }
}

// ---------------- launch ----------------
extern "C" void kernel_launch(void* const* d_in, const int* in_sizes, int n_in,
                              void* d_out, int out_size) {
    const float* adj  = (const float*)d_in[0];
    const float* feat = (const float*)d_in[1];
    const float* W0   = (const float*)d_in[2];
    const float* a1_0 = (const float*)d_in[3];
    const float* a2_0 = (const float*)d_in[4];
    const float* Wout = (const float*)d_in[5];
    const float* a1o  = (const float*)d_in[6];
    const float* a2o  = (const float*)d_in[7];
    float* out = (float*)d_out;

    k_prep<<<512, 256>>>(W0, feat);
    k_gemm<<<(NV / 64) * NHEAD, 256>>>(a1_0, a2_0);
    k_attn_hidden<<<NV, 256>>>(adj, Wout, a1o, a2o);
    k_attn_out<<<NV / ROWS_PER_OUT_BLOCK, 256>>>(adj, out);
}